// round 2
// baseline (speedup 1.0000x reference)
#include <cuda_runtime.h>
#include <cstddef>

#define T_TOK 2048
#define DIM   1024
#define HID   4096
#define NE    7        // routed experts (expert index 7 = "none routed")
#define ALPHA 2.0f

#define BM 64
#define BN 64
#define BK 16

// Scratch (device globals: allowed; no runtime allocation)
__device__ float g_hs[(size_t)T_TOK * HID];   // shared-expert hidden (up * silu(gate))
__device__ float g_hr[(size_t)T_TOK * HID];   // routed hidden, pre-scaled by ALPHA*p_top1
__device__ int   g_expert[T_TOK];
__device__ float g_scale[T_TOK];
__device__ int   g_cnt[NE];
__device__ int   g_list[NE * T_TOK];

// ---------------------------------------------------------------------------
// Router: one warp per token. logits = x[t] @ w_router ([1024,8]),
// softmax fp32, top-1 (first index wins ties, matching lax.top_k).
// ---------------------------------------------------------------------------
__global__ void router_kernel(const float* __restrict__ x,
                              const float* __restrict__ wr) {
    int warp = (blockIdx.x * blockDim.x + threadIdx.x) >> 5;
    int lane = threadIdx.x & 31;
    if (warp >= T_TOK) return;
    const float* xr = x + (size_t)warp * DIM;
    float acc[8] = {0.f, 0.f, 0.f, 0.f, 0.f, 0.f, 0.f, 0.f};
    for (int d = lane; d < DIM; d += 32) {
        float xv = xr[d];
        const float4* w4 = reinterpret_cast<const float4*>(wr + (size_t)d * 8);
        float4 a = w4[0], b = w4[1];
        acc[0] += xv * a.x; acc[1] += xv * a.y; acc[2] += xv * a.z; acc[3] += xv * a.w;
        acc[4] += xv * b.x; acc[5] += xv * b.y; acc[6] += xv * b.z; acc[7] += xv * b.w;
    }
#pragma unroll
    for (int e = 0; e < 8; e++)
#pragma unroll
        for (int o = 16; o > 0; o >>= 1)
            acc[e] += __shfl_down_sync(0xffffffffu, acc[e], o);
    if (lane == 0) {
        float m = acc[0]; int a = 0;
#pragma unroll
        for (int e = 1; e < 8; e++) if (acc[e] > m) { m = acc[e]; a = e; }
        float s = 0.f;
#pragma unroll
        for (int e = 0; e < 8; e++) s += __expf(acc[e] - m);
        float p = 1.0f / s;            // prob of the max logit
        g_expert[warp] = a;
        g_scale[warp]  = ALPHA * p;    // used only if a < NE
    }
}

__global__ void zero_cnt_kernel() {
    if (threadIdx.x < NE) g_cnt[threadIdx.x] = 0;
}

__global__ void build_lists_kernel() {
    int t = blockIdx.x * blockDim.x + threadIdx.x;
    if (t >= T_TOK) return;
    int e = g_expert[t];
    if (e < NE) {
        int pos = atomicAdd(&g_cnt[e], 1);
        g_list[e * T_TOK + pos] = t;
    }
}

// ---------------------------------------------------------------------------
// Fused up+gate GEMM + SwiGLU. grid.z in [0,7]: z<7 routed (gathered token
// rows, output pre-scaled by ALPHA*p into g_hr), z==7 shared (all tokens,
// output to g_hs). BMxBNxBK = 64x64x16, 256 threads, 4x4 per thread (x2 mats).
// ---------------------------------------------------------------------------
__global__ void upgate_kernel(const float* __restrict__ x,
                              const float* __restrict__ w_up,
                              const float* __restrict__ w_gate,
                              const float* __restrict__ ws_up,
                              const float* __restrict__ ws_gate) {
    const int e = blockIdx.z;
    const bool is_shared = (e == NE);
    const int cnt = is_shared ? T_TOK : g_cnt[e];
    const int m0 = blockIdx.y * BM;
    if (m0 >= cnt) return;
    const int n0 = blockIdx.x * BN;

    const float* Bu = is_shared ? ws_up   : (w_up   + (size_t)e * DIM * HID);
    const float* Bg = is_shared ? ws_gate : (w_gate + (size_t)e * DIM * HID);

    __shared__ float As [BK][BM];
    __shared__ float Bus[BK][BN];
    __shared__ float Bgs[BK][BN];
    __shared__ int   toks[BM];

    const int tid = threadIdx.x;          // 256
    if (tid < BM) {
        int r = m0 + tid;
        toks[tid] = is_shared ? r : (r < cnt ? g_list[e * T_TOK + r] : -1);
    }
    __syncthreads();

    const int arow = tid >> 2, ak = (tid & 3) * 4;     // A: 64 rows x 4 float4
    const int brow = tid >> 4, bn = (tid & 15) * 4;    // B: 16 rows x 16 float4
    const int ty = tid >> 4, tx = tid & 15;

    int tka = toks[arow]; if (tka < 0) tka = 0;        // pad rows read token 0
    const float* arow_ptr = x + (size_t)tka * DIM;

    float acc_u[4][4] = {}, acc_g[4][4] = {};

    for (int k0 = 0; k0 < DIM; k0 += BK) {
        float4 av = *reinterpret_cast<const float4*>(arow_ptr + k0 + ak);
        As[ak + 0][arow] = av.x; As[ak + 1][arow] = av.y;
        As[ak + 2][arow] = av.z; As[ak + 3][arow] = av.w;
        *reinterpret_cast<float4*>(&Bus[brow][bn]) =
            *reinterpret_cast<const float4*>(Bu + (size_t)(k0 + brow) * HID + n0 + bn);
        *reinterpret_cast<float4*>(&Bgs[brow][bn]) =
            *reinterpret_cast<const float4*>(Bg + (size_t)(k0 + brow) * HID + n0 + bn);
        __syncthreads();
#pragma unroll
        for (int k = 0; k < BK; k++) {
            float4 a4  = *reinterpret_cast<const float4*>(&As [k][ty * 4]);
            float4 bu4 = *reinterpret_cast<const float4*>(&Bus[k][tx * 4]);
            float4 bg4 = *reinterpret_cast<const float4*>(&Bgs[k][tx * 4]);
            float a[4]  = {a4.x, a4.y, a4.z, a4.w};
            float bu[4] = {bu4.x, bu4.y, bu4.z, bu4.w};
            float bg[4] = {bg4.x, bg4.y, bg4.z, bg4.w};
#pragma unroll
            for (int i = 0; i < 4; i++)
#pragma unroll
                for (int j = 0; j < 4; j++) {
                    acc_u[i][j] += a[i] * bu[j];
                    acc_g[i][j] += a[i] * bg[j];
                }
        }
        __syncthreads();
    }

    float* dst = is_shared ? g_hs : g_hr;
#pragma unroll
    for (int i = 0; i < 4; i++) {
        int tk = toks[ty * 4 + i];
        if (tk < 0) continue;
        float sc = is_shared ? 1.0f : g_scale[tk];
        float h[4];
#pragma unroll
        for (int j = 0; j < 4; j++) {
            float u = acc_u[i][j], g = acc_g[i][j];
            float sg = 1.0f / (1.0f + __expf(-g));
            h[j] = sc * u * g * sg;                 // sc * up * silu(gate)
        }
        *reinterpret_cast<float4*>(dst + (size_t)tk * HID + n0 + tx * 4) =
            make_float4(h[0], h[1], h[2], h[3]);
    }
}

// ---------------------------------------------------------------------------
// Shared-expert down projection: out = g_hs @ ws_down  (plain store; covers
// every output element, so also initializes out).
// ---------------------------------------------------------------------------
__global__ void down_shared_kernel(const float* __restrict__ ws_down,
                                   float* __restrict__ out) {
    const int m0 = blockIdx.y * BM, n0 = blockIdx.x * BN;
    __shared__ float As[BK][BM];
    __shared__ float Bs[BK][BN];
    const int tid = threadIdx.x;
    const int arow = tid >> 2, ak = (tid & 3) * 4;
    const int brow = tid >> 4, bn = (tid & 15) * 4;
    const int ty = tid >> 4, tx = tid & 15;
    const float* arow_ptr = g_hs + (size_t)(m0 + arow) * HID;

    float acc[4][4] = {};
    for (int k0 = 0; k0 < HID; k0 += BK) {
        float4 av = *reinterpret_cast<const float4*>(arow_ptr + k0 + ak);
        As[ak + 0][arow] = av.x; As[ak + 1][arow] = av.y;
        As[ak + 2][arow] = av.z; As[ak + 3][arow] = av.w;
        *reinterpret_cast<float4*>(&Bs[brow][bn]) =
            *reinterpret_cast<const float4*>(ws_down + (size_t)(k0 + brow) * DIM + n0 + bn);
        __syncthreads();
#pragma unroll
        for (int k = 0; k < BK; k++) {
            float4 a4 = *reinterpret_cast<const float4*>(&As[k][ty * 4]);
            float4 b4 = *reinterpret_cast<const float4*>(&Bs[k][tx * 4]);
            float a[4] = {a4.x, a4.y, a4.z, a4.w};
            float b[4] = {b4.x, b4.y, b4.z, b4.w};
#pragma unroll
            for (int i = 0; i < 4; i++)
#pragma unroll
                for (int j = 0; j < 4; j++) acc[i][j] += a[i] * b[j];
        }
        __syncthreads();
    }
#pragma unroll
    for (int i = 0; i < 4; i++) {
        *reinterpret_cast<float4*>(out + (size_t)(m0 + ty * 4 + i) * DIM + n0 + tx * 4) =
            make_float4(acc[i][0], acc[i][1], acc[i][2], acc[i][3]);
    }
}

// ---------------------------------------------------------------------------
// Routed down projection: out[tok] += g_hr[tok] @ w_down[e] (g_hr pre-scaled).
// grid.z = expert; gathered token rows; each token in exactly one expert list
// so the += has no cross-block races; stream order puts it after down_shared.
// ---------------------------------------------------------------------------
__global__ void down_routed_kernel(const float* __restrict__ w_down,
                                   float* __restrict__ out) {
    const int e = blockIdx.z;
    const int cnt = g_cnt[e];
    const int m0 = blockIdx.y * BM;
    if (m0 >= cnt) return;
    const int n0 = blockIdx.x * BN;
    const float* Bp = w_down + (size_t)e * HID * DIM;

    __shared__ float As[BK][BM];
    __shared__ float Bs[BK][BN];
    __shared__ int   toks[BM];

    const int tid = threadIdx.x;
    if (tid < BM) {
        int r = m0 + tid;
        toks[tid] = (r < cnt) ? g_list[e * T_TOK + r] : -1;
    }
    __syncthreads();

    const int arow = tid >> 2, ak = (tid & 3) * 4;
    const int brow = tid >> 4, bn = (tid & 15) * 4;
    const int ty = tid >> 4, tx = tid & 15;
    int tka = toks[arow]; if (tka < 0) tka = 0;
    const float* arow_ptr = g_hr + (size_t)tka * HID;

    float acc[4][4] = {};
    for (int k0 = 0; k0 < HID; k0 += BK) {
        float4 av = *reinterpret_cast<const float4*>(arow_ptr + k0 + ak);
        As[ak + 0][arow] = av.x; As[ak + 1][arow] = av.y;
        As[ak + 2][arow] = av.z; As[ak + 3][arow] = av.w;
        *reinterpret_cast<float4*>(&Bs[brow][bn]) =
            *reinterpret_cast<const float4*>(Bp + (size_t)(k0 + brow) * DIM + n0 + bn);
        __syncthreads();
#pragma unroll
        for (int k = 0; k < BK; k++) {
            float4 a4 = *reinterpret_cast<const float4*>(&As[k][ty * 4]);
            float4 b4 = *reinterpret_cast<const float4*>(&Bs[k][tx * 4]);
            float a[4] = {a4.x, a4.y, a4.z, a4.w};
            float b[4] = {b4.x, b4.y, b4.z, b4.w};
#pragma unroll
            for (int i = 0; i < 4; i++)
#pragma unroll
                for (int j = 0; j < 4; j++) acc[i][j] += a[i] * b[j];
        }
        __syncthreads();
    }
#pragma unroll
    for (int i = 0; i < 4; i++) {
        int tk = toks[ty * 4 + i];
        if (tk < 0) continue;
        float4* p = reinterpret_cast<float4*>(out + (size_t)tk * DIM + n0 + tx * 4);
        float4 v = *p;
        v.x += acc[i][0]; v.y += acc[i][1]; v.z += acc[i][2]; v.w += acc[i][3];
        *p = v;
    }
}

// ---------------------------------------------------------------------------
extern "C" void kernel_launch(void* const* d_in, const int* in_sizes, int n_in,
                              void* d_out, int out_size) {
    const float* x       = (const float*)d_in[0];
    const float* wr      = (const float*)d_in[1];
    const float* w_up    = (const float*)d_in[2];
    const float* w_gate  = (const float*)d_in[3];
    const float* w_down  = (const float*)d_in[4];
    const float* ws_up   = (const float*)d_in[5];
    const float* ws_gate = (const float*)d_in[6];
    const float* ws_down = (const float*)d_in[7];
    float* out = (float*)d_out;

    router_kernel<<<T_TOK / 8, 256>>>(x, wr);
    zero_cnt_kernel<<<1, 32>>>();
    build_lists_kernel<<<T_TOK / 256, 256>>>();

    dim3 g_ug(HID / BN, T_TOK / BM, NE + 1);     // (64, 32, 8)
    upgate_kernel<<<g_ug, 256>>>(x, w_up, w_gate, ws_up, ws_gate);

    dim3 g_ds(DIM / BN, T_TOK / BM, 1);          // (16, 32)
    down_shared_kernel<<<g_ds, 256>>>(ws_down, out);

    dim3 g_dr(DIM / BN, T_TOK / BM, NE);         // (16, 32, 7)
    down_routed_kernel<<<g_dr, 256>>>(w_down, out);
}

// round 11
// speedup vs baseline: 1.0630x; 1.0630x over previous
#include <cuda_runtime.h>
#include <cstdint>
#include <cstddef>

#define T_TOK 2048
#define DIM   1024
#define HID   4096
#define NE    7        // routed experts (expert index 7 = "none routed")
#define ALPHA 2.0f

#define BM 64
#define BN 64
#define BK 16

typedef unsigned long long u64;

// Scratch (device globals: allowed; no runtime allocation)
__device__ float g_hs[(size_t)T_TOK * HID];   // shared-expert hidden (up * silu(gate))
__device__ float g_hr[(size_t)T_TOK * HID];   // routed hidden, pre-scaled by ALPHA*p_top1
__device__ int   g_expert[T_TOK];
__device__ float g_scale[T_TOK];
__device__ int   g_cnt[NE];
__device__ int   g_list[NE * T_TOK];

// ---------------------------------------------------------------------------
// f32x2 helpers (Blackwell packed fp32 FFMA2 — only reachable via explicit PTX)
// ---------------------------------------------------------------------------
__device__ __forceinline__ void fma2(u64& c, u64 a, u64 b) {
    asm("fma.rn.f32x2 %0, %1, %2, %0;" : "+l"(c) : "l"(a), "l"(b));
}
__device__ __forceinline__ u64 pk(float x, float y) {
    u64 r; asm("mov.b64 %0, {%1, %2};" : "=l"(r) : "f"(x), "f"(y)); return r;
}
__device__ __forceinline__ void upk(u64 v, float& x, float& y) {
    asm("mov.b64 {%0, %1}, %2;" : "=f"(x), "=f"(y) : "l"(v));
}

// ---------------------------------------------------------------------------
// Router: one warp per token (verified R2).
// ---------------------------------------------------------------------------
__global__ void router_kernel(const float* __restrict__ x,
                              const float* __restrict__ wr) {
    int warp = (blockIdx.x * blockDim.x + threadIdx.x) >> 5;
    int lane = threadIdx.x & 31;
    if (warp >= T_TOK) return;
    const float* xr = x + (size_t)warp * DIM;
    float acc[8] = {0.f, 0.f, 0.f, 0.f, 0.f, 0.f, 0.f, 0.f};
    for (int d = lane; d < DIM; d += 32) {
        float xv = xr[d];
        const float4* w4 = reinterpret_cast<const float4*>(wr + (size_t)d * 8);
        float4 a = w4[0], b = w4[1];
        acc[0] += xv * a.x; acc[1] += xv * a.y; acc[2] += xv * a.z; acc[3] += xv * a.w;
        acc[4] += xv * b.x; acc[5] += xv * b.y; acc[6] += xv * b.z; acc[7] += xv * b.w;
    }
#pragma unroll
    for (int e = 0; e < 8; e++)
#pragma unroll
        for (int o = 16; o > 0; o >>= 1)
            acc[e] += __shfl_down_sync(0xffffffffu, acc[e], o);
    if (lane == 0) {
        float m = acc[0]; int a = 0;
#pragma unroll
        for (int e = 1; e < 8; e++) if (acc[e] > m) { m = acc[e]; a = e; }
        float s = 0.f;
#pragma unroll
        for (int e = 0; e < 8; e++) s += __expf(acc[e] - m);
        float p = 1.0f / s;
        g_expert[warp] = a;
        g_scale[warp]  = ALPHA * p;
    }
}

__global__ void zero_cnt_kernel() {
    if (threadIdx.x < NE) g_cnt[threadIdx.x] = 0;
}

__global__ void build_lists_kernel() {
    int t = blockIdx.x * blockDim.x + threadIdx.x;
    if (t >= T_TOK) return;
    int e = g_expert[t];
    if (e < NE) {
        int pos = atomicAdd(&g_cnt[e], 1);
        g_list[e * T_TOK + pos] = t;
    }
}

// ---------------------------------------------------------------------------
// Fused up+gate GEMM + SwiGLU — VERIFIED R2 FFMA VERSION, UNCHANGED.
// ---------------------------------------------------------------------------
__global__ void upgate_kernel(const float* __restrict__ x,
                              const float* __restrict__ w_up,
                              const float* __restrict__ w_gate,
                              const float* __restrict__ ws_up,
                              const float* __restrict__ ws_gate) {
    const int e = blockIdx.z;
    const bool is_shared = (e == NE);
    const int cnt = is_shared ? T_TOK : g_cnt[e];
    const int m0 = blockIdx.y * BM;
    if (m0 >= cnt) return;
    const int n0 = blockIdx.x * BN;

    const float* Bu = is_shared ? ws_up   : (w_up   + (size_t)e * DIM * HID);
    const float* Bg = is_shared ? ws_gate : (w_gate + (size_t)e * DIM * HID);

    __shared__ float As [BK][BM];
    __shared__ float Bus[BK][BN];
    __shared__ float Bgs[BK][BN];
    __shared__ int   toks[BM];

    const int tid = threadIdx.x;
    if (tid < BM) {
        int r = m0 + tid;
        toks[tid] = is_shared ? r : (r < cnt ? g_list[e * T_TOK + r] : -1);
    }
    __syncthreads();

    const int arow = tid >> 2, ak = (tid & 3) * 4;
    const int brow = tid >> 4, bn = (tid & 15) * 4;
    const int ty = tid >> 4, tx = tid & 15;

    int tka = toks[arow]; if (tka < 0) tka = 0;
    const float* arow_ptr = x + (size_t)tka * DIM;

    float acc_u[4][4] = {}, acc_g[4][4] = {};

    for (int k0 = 0; k0 < DIM; k0 += BK) {
        float4 av = *reinterpret_cast<const float4*>(arow_ptr + k0 + ak);
        As[ak + 0][arow] = av.x; As[ak + 1][arow] = av.y;
        As[ak + 2][arow] = av.z; As[ak + 3][arow] = av.w;
        *reinterpret_cast<float4*>(&Bus[brow][bn]) =
            *reinterpret_cast<const float4*>(Bu + (size_t)(k0 + brow) * HID + n0 + bn);
        *reinterpret_cast<float4*>(&Bgs[brow][bn]) =
            *reinterpret_cast<const float4*>(Bg + (size_t)(k0 + brow) * HID + n0 + bn);
        __syncthreads();
#pragma unroll
        for (int k = 0; k < BK; k++) {
            float4 a4  = *reinterpret_cast<const float4*>(&As [k][ty * 4]);
            float4 bu4 = *reinterpret_cast<const float4*>(&Bus[k][tx * 4]);
            float4 bg4 = *reinterpret_cast<const float4*>(&Bgs[k][tx * 4]);
            float a[4]  = {a4.x, a4.y, a4.z, a4.w};
            float bu[4] = {bu4.x, bu4.y, bu4.z, bu4.w};
            float bg[4] = {bg4.x, bg4.y, bg4.z, bg4.w};
#pragma unroll
            for (int i = 0; i < 4; i++)
#pragma unroll
                for (int j = 0; j < 4; j++) {
                    acc_u[i][j] += a[i] * bu[j];
                    acc_g[i][j] += a[i] * bg[j];
                }
        }
        __syncthreads();
    }

    float* dst = is_shared ? g_hs : g_hr;
#pragma unroll
    for (int i = 0; i < 4; i++) {
        int tk = toks[ty * 4 + i];
        if (tk < 0) continue;
        float sc = is_shared ? 1.0f : g_scale[tk];
        float h[4];
#pragma unroll
        for (int j = 0; j < 4; j++) {
            float u = acc_u[i][j], g = acc_g[i][j];
            float sg = 1.0f / (1.0f + __expf(-g));
            h[j] = sc * u * g * sg;
        }
        *reinterpret_cast<float4*>(dst + (size_t)tk * HID + n0 + tx * 4) =
            make_float4(h[0], h[1], h[2], h[3]);
    }
}

// ---------------------------------------------------------------------------
// Shared-expert down projection — R2 SKELETON; inner product switched to
// fma.rn.f32x2 (THE UNIT UNDER TEST). Same loads/smem/epilogue shape.
// ---------------------------------------------------------------------------
__global__ void down_shared_kernel(const float* __restrict__ ws_down,
                                   float* __restrict__ out) {
    const int m0 = blockIdx.y * BM, n0 = blockIdx.x * BN;
    __shared__ float As[BK][BM];
    __shared__ float Bs[BK][BN];
    const int tid = threadIdx.x;
    const int arow = tid >> 2, ak = (tid & 3) * 4;
    const int brow = tid >> 4, bn = (tid & 15) * 4;
    const int ty = tid >> 4, tx = tid & 15;
    const float* arow_ptr = g_hs + (size_t)(m0 + arow) * HID;

    u64 acc2[4][2] = {};
    for (int k0 = 0; k0 < HID; k0 += BK) {
        float4 av = *reinterpret_cast<const float4*>(arow_ptr + k0 + ak);
        As[ak + 0][arow] = av.x; As[ak + 1][arow] = av.y;
        As[ak + 2][arow] = av.z; As[ak + 3][arow] = av.w;
        *reinterpret_cast<float4*>(&Bs[brow][bn]) =
            *reinterpret_cast<const float4*>(ws_down + (size_t)(k0 + brow) * DIM + n0 + bn);
        __syncthreads();
#pragma unroll
        for (int k = 0; k < BK; k++) {
            float4 a4 = *reinterpret_cast<const float4*>(&As[k][ty * 4]);
            float4 b4 = *reinterpret_cast<const float4*>(&Bs[k][tx * 4]);
            u64 b01 = pk(b4.x, b4.y), b23 = pk(b4.z, b4.w);
            float a[4] = {a4.x, a4.y, a4.z, a4.w};
#pragma unroll
            for (int i = 0; i < 4; i++) {
                u64 aa = pk(a[i], a[i]);
                fma2(acc2[i][0], aa, b01);
                fma2(acc2[i][1], aa, b23);
            }
        }
        __syncthreads();
    }
#pragma unroll
    for (int i = 0; i < 4; i++) {
        float r0, r1, r2, r3;
        upk(acc2[i][0], r0, r1);
        upk(acc2[i][1], r2, r3);
        *reinterpret_cast<float4*>(out + (size_t)(m0 + ty * 4 + i) * DIM + n0 + tx * 4) =
            make_float4(r0, r1, r2, r3);
    }
}

// ---------------------------------------------------------------------------
// Routed down projection — R2 SKELETON; f32x2 inner product; out += .
// ---------------------------------------------------------------------------
__global__ void down_routed_kernel(const float* __restrict__ w_down,
                                   float* __restrict__ out) {
    const int e = blockIdx.z;
    const int cnt = g_cnt[e];
    const int m0 = blockIdx.y * BM;
    if (m0 >= cnt) return;
    const int n0 = blockIdx.x * BN;
    const float* Bp = w_down + (size_t)e * HID * DIM;

    __shared__ float As[BK][BM];
    __shared__ float Bs[BK][BN];
    __shared__ int   toks[BM];

    const int tid = threadIdx.x;
    if (tid < BM) {
        int r = m0 + tid;
        toks[tid] = (r < cnt) ? g_list[e * T_TOK + r] : -1;
    }
    __syncthreads();

    const int arow = tid >> 2, ak = (tid & 3) * 4;
    const int brow = tid >> 4, bn = (tid & 15) * 4;
    const int ty = tid >> 4, tx = tid & 15;
    int tka = toks[arow]; if (tka < 0) tka = 0;
    const float* arow_ptr = g_hr + (size_t)tka * HID;

    u64 acc2[4][2] = {};
    for (int k0 = 0; k0 < HID; k0 += BK) {
        float4 av = *reinterpret_cast<const float4*>(arow_ptr + k0 + ak);
        As[ak + 0][arow] = av.x; As[ak + 1][arow] = av.y;
        As[ak + 2][arow] = av.z; As[ak + 3][arow] = av.w;
        *reinterpret_cast<float4*>(&Bs[brow][bn]) =
            *reinterpret_cast<const float4*>(Bp + (size_t)(k0 + brow) * DIM + n0 + bn);
        __syncthreads();
#pragma unroll
        for (int k = 0; k < BK; k++) {
            float4 a4 = *reinterpret_cast<const float4*>(&As[k][ty * 4]);
            float4 b4 = *reinterpret_cast<const float4*>(&Bs[k][tx * 4]);
            u64 b01 = pk(b4.x, b4.y), b23 = pk(b4.z, b4.w);
            float a[4] = {a4.x, a4.y, a4.z, a4.w};
#pragma unroll
            for (int i = 0; i < 4; i++) {
                u64 aa = pk(a[i], a[i]);
                fma2(acc2[i][0], aa, b01);
                fma2(acc2[i][1], aa, b23);
            }
        }
        __syncthreads();
    }
#pragma unroll
    for (int i = 0; i < 4; i++) {
        int tk = toks[ty * 4 + i];
        if (tk < 0) continue;
        float r0, r1, r2, r3;
        upk(acc2[i][0], r0, r1);
        upk(acc2[i][1], r2, r3);
        float4* p = reinterpret_cast<float4*>(out + (size_t)tk * DIM + n0 + tx * 4);
        float4 v = *p;
        v.x += r0; v.y += r1; v.z += r2; v.w += r3;
        *p = v;
    }
}

// ---------------------------------------------------------------------------
extern "C" void kernel_launch(void* const* d_in, const int* in_sizes, int n_in,
                              void* d_out, int out_size) {
    const float* x       = (const float*)d_in[0];
    const float* wr      = (const float*)d_in[1];
    const float* w_up    = (const float*)d_in[2];
    const float* w_gate  = (const float*)d_in[3];
    const float* w_down  = (const float*)d_in[4];
    const float* ws_up   = (const float*)d_in[5];
    const float* ws_gate = (const float*)d_in[6];
    const float* ws_down = (const float*)d_in[7];
    float* out = (float*)d_out;

    router_kernel<<<T_TOK / 8, 256>>>(x, wr);
    zero_cnt_kernel<<<1, 32>>>();
    build_lists_kernel<<<T_TOK / 256, 256>>>();

    dim3 g_ug(HID / BN, T_TOK / BM, NE + 1);     // (64, 32, 8)
    upgate_kernel<<<g_ug, 256>>>(x, w_up, w_gate, ws_up, ws_gate);

    dim3 g_ds(DIM / BN, T_TOK / BM, 1);          // (16, 32)
    down_shared_kernel<<<g_ds, 256>>>(ws_down, out);

    dim3 g_dr(DIM / BN, T_TOK / BM, NE);         // (16, 32, 7)
    down_routed_kernel<<<g_dr, 256>>>(w_down, out);
}